// round 1
// baseline (speedup 1.0000x reference)
#include <cuda_runtime.h>
#include <cstdint>

// QuadraticConv2D: out[m, o] = sum_{p=(i,j), i<=j} sum_c S_i[m,c]*S_j[m,c] * W[p,c,o]
//   m = flattened (b,h,w) over [8,56,56];  S_0 = 1, S_k (k=1..9) = 3x3 shifted patch
//   (zero-padded 'same').  Pure fp32 SIMT GEMM with on-the-fly A generation.

#define BDIM   256
#define CH      64
#define OD     128
#define HW      56
#define NPOS  (8 * 56 * 56)    // 25088
#define MT      64             // positions per block
#define ASTRIDE 68             // padded A row stride (floats) to dodge bank conflicts

#define SMEM_A_FLOATS (CH * ASTRIDE)   // 4352
#define SMEM_W_FLOATS (CH * OD)        // 8192
#define SMEM_FLOATS   (SMEM_A_FLOATS + SMEM_W_FLOATS + 64 + 64)
#define SMEM_BYTES    (SMEM_FLOATS * 4)   // 50688

// pair tables: (i,j) for i in 0..9, j in i..9  (55 pairs, same order as reference)
__constant__ unsigned char cII[55] = {
    0,0,0,0,0,0,0,0,0,0,
    1,1,1,1,1,1,1,1,1,
    2,2,2,2,2,2,2,2,
    3,3,3,3,3,3,3,
    4,4,4,4,4,4,
    5,5,5,5,5,
    6,6,6,6,
    7,7,7,
    8,8,
    9};
__constant__ unsigned char cJJ[55] = {
    0,1,2,3,4,5,6,7,8,9,
    1,2,3,4,5,6,7,8,9,
    2,3,4,5,6,7,8,9,
    3,4,5,6,7,8,9,
    4,5,6,7,8,9,
    5,6,7,8,9,
    6,7,8,9,
    7,8,9,
    8,9,
    9};

__global__ void __launch_bounds__(BDIM, 3)
qconv_kernel(const float* __restrict__ in,   // [8,56,56,64]
             const float* __restrict__ wt,   // [55,64,128]
             float* __restrict__ out)        // [8,56,56,128]
{
    extern __shared__ float smem[];
    float* Ash   = smem;                                   // [64][68]  A tile: quad feats
    float* Wsh   = smem + SMEM_A_FLOATS;                   // [64][128] weight slice
    int*   mbase = (int*)(smem + SMEM_A_FLOATS + SMEM_W_FLOATS);  // [64] input base idx
    int*   mmask = mbase + 64;                                    // [64] 9-bit validity

    const int tid = threadIdx.x;
    const int gm0 = blockIdx.x * MT;

    // ---- per-block position metadata (base offset + 3x3 validity mask) ----
    if (tid < MT) {
        int gm  = gm0 + tid;
        int b   = gm / (HW * HW);
        int rem = gm - b * HW * HW;
        int h   = rem / HW;
        int w   = rem - h * HW;
        mbase[tid] = ((b * HW + (h - 1)) * HW + (w - 1)) * CH;
        int mask = 0;
        #pragma unroll
        for (int kk = 0; kk < 9; kk++) {
            int dr = kk / 3, dc = kk % 3;
            int hh = h + dr - 1, ww = w + dc - 1;
            if (hh >= 0 && hh < HW && ww >= 0 && ww < HW) mask |= (1 << kk);
        }
        mmask[tid] = mask;
    }

    // A-generation mapping: each thread owns channel ac, 16 positions (mseg)
    const int ac   = tid & 63;
    const int mseg = tid >> 6;
    // GEMM mapping: thread covers 4 positions (mg) x 8 outputs {og*4.., 64+og*4..}
    const int og = tid & 15;
    const int mg = tid >> 4;

    float acc[4][8];
    #pragma unroll
    for (int v = 0; v < 4; v++)
        #pragma unroll
        for (int u = 0; u < 8; u++) acc[v][u] = 0.f;

    __syncthreads();   // metadata visible

    for (int p = 0; p < 55; p++) {
        const int i = cII[p], j = cJJ[p];
        const int kkj = j - 1;
        const int kki = i - 1;
        const int offj = (j > 0) ? ((kkj / 3) * HW + (kkj % 3)) * CH + ac : 0;
        const int offi = (i > 0) ? ((kki / 3) * HW + (kki % 3)) * CH + ac : 0;

        // ---- build A tile: A[c][m] = S_i(m,c) * S_j(m,c) ----
        #pragma unroll
        for (int g = 0; g < 4; g++) {
            const int m0 = mseg * 16 + g * 4;
            float av[4];
            #pragma unroll
            for (int v = 0; v < 4; v++) {
                const int mi = m0 + v;
                float a;
                if (p == 0) {
                    a = 1.f;                       // (ones, ones) pair
                } else {
                    const int base = mbase[mi];    // broadcast LDS
                    const int mask = mmask[mi];
                    float sj = ((mask >> kkj) & 1) ? __ldg(in + base + offj) : 0.f;
                    if (i == 0) {
                        a = sj;                    // linear term
                    } else {
                        float si = ((mask >> kki) & 1) ? __ldg(in + base + offi) : 0.f;
                        a = si * sj;               // quadratic term
                    }
                }
                av[v] = a;
            }
            *(float4*)&Ash[ac * ASTRIDE + m0] = make_float4(av[0], av[1], av[2], av[3]);
        }

        // ---- stage weight slice W[p] : 64x128 floats ----
        {
            const float4* src = (const float4*)(wt + (size_t)p * CH * OD);
            float4*       dst = (float4*)Wsh;
            #pragma unroll
            for (int t = 0; t < 8; t++) dst[tid + t * BDIM] = src[tid + t * BDIM];
        }
        __syncthreads();

        // ---- GEMM accumulate: 32 FFMA per 3 LDS.128 ----
        #pragma unroll 8
        for (int c = 0; c < CH; c++) {
            float4 a4 = *(const float4*)&Ash[c * ASTRIDE + mg * 4];
            float4 w0 = *(const float4*)&Wsh[c * OD + og * 4];
            float4 w1 = *(const float4*)&Wsh[c * OD + 64 + og * 4];
            float am[4] = {a4.x, a4.y, a4.z, a4.w};
            float wv[8] = {w0.x, w0.y, w0.z, w0.w, w1.x, w1.y, w1.z, w1.w};
            #pragma unroll
            for (int v = 0; v < 4; v++)
                #pragma unroll
                for (int u = 0; u < 8; u++)
                    acc[v][u] = fmaf(am[v], wv[u], acc[v][u]);
        }
        __syncthreads();   // safe to overwrite Ash/Wsh next p
    }

    // ---- epilogue: every position in this block is valid (flat M) ----
    float* op = out + (size_t)gm0 * OD;
    #pragma unroll
    for (int v = 0; v < 4; v++) {
        const int mi = mg * 4 + v;
        *(float4*)&op[mi * OD + og * 4] =
            make_float4(acc[v][0], acc[v][1], acc[v][2], acc[v][3]);
        *(float4*)&op[mi * OD + 64 + og * 4] =
            make_float4(acc[v][4], acc[v][5], acc[v][6], acc[v][7]);
    }
}

extern "C" void kernel_launch(void* const* d_in, const int* in_sizes, int n_in,
                              void* d_out, int out_size)
{
    const float* in = (const float*)d_in[0];
    const float* wt = (const float*)d_in[1];
    // defensive: inputs = 1605632 elems, kernel = 450560 elems
    if (n_in >= 2 && in_sizes[0] == 55 * CH * OD) {
        const float* t = in; in = wt; wt = t;
    }
    float* out = (float*)d_out;

    cudaFuncSetAttribute(qconv_kernel,
                         cudaFuncAttributeMaxDynamicSharedMemorySize, SMEM_BYTES);
    qconv_kernel<<<NPOS / MT, BDIM, SMEM_BYTES>>>(in, wt, out);
}

// round 3
// speedup vs baseline: 1.7583x; 1.7583x over previous
#include <cuda_runtime.h>
#include <cuda_bf16.h>
#include <cstdint>

// ============================================================================
// QuadraticConv2D via mma.sync (HMMA) bf16 split-precision GEMM.
// out[m,o] = sum_{p=(i,j)} sum_c S_i[m,c]*S_j[m,c] * W[p,c,o]
// fp32 operands split x = hi + lo (bf16); per product: hi*hi + hi*lo + lo*hi.
// All instructions are portable (non-'a') PTX: ldmatrix + mma.sync.m16n8k16.
// ============================================================================

#define HW     56
#define CH     64
#define OD     128
#define NPOS   (8 * 56 * 56)      // 25088
#define MT     64                 // M rows per CTA
#define NTILES (NPOS / MT)        // 392
#define BDIM   128
#define NPAIRS 55

#define ASTR   144                // A row stride bytes (72 bf16, conflict-free)
#define BSTR   272                // B row stride bytes (136 bf16, conflict-free)

// SMEM layout (bytes)
#define AH_OFF 0                  // 64 x 144 = 9216
#define AL_OFF 9216
#define BH_OFF 18432              // 64 x 272 = 17408
#define BL_OFF 35840
#define MB_OFF 53248              // mbase[64] int
#define MK_OFF 53504              // mmask[64] int
#define SMEM_TOTAL 53760

// pre-split weights, padded layout [p][c*136 + o] bf16
__device__ __align__(16) __nv_bfloat16 g_Bhi[NPAIRS][CH * (BSTR / 2)];
__device__ __align__(16) __nv_bfloat16 g_Blo[NPAIRS][CH * (BSTR / 2)];

__constant__ unsigned char cII[55] = {
    0,0,0,0,0,0,0,0,0,0, 1,1,1,1,1,1,1,1,1, 2,2,2,2,2,2,2,2,
    3,3,3,3,3,3,3, 4,4,4,4,4,4, 5,5,5,5,5, 6,6,6,6, 7,7,7, 8,8, 9};
__constant__ unsigned char cJJ[55] = {
    0,1,2,3,4,5,6,7,8,9, 1,2,3,4,5,6,7,8,9, 2,3,4,5,6,7,8,9,
    3,4,5,6,7,8,9, 4,5,6,7,8,9, 5,6,7,8,9, 6,7,8,9, 7,8,9, 8,9, 9};

__device__ __forceinline__ uint32_t smem_to_u32(const void* p) {
    uint32_t a;
    asm("{ .reg .u64 t; cvta.to.shared.u64 t, %1; cvt.u32.u64 %0, t; }"
        : "=r"(a) : "l"(p));
    return a;
}

#define LDSM_X4(r, addr) \
    asm volatile("ldmatrix.sync.aligned.m8n8.x4.shared.b16 {%0,%1,%2,%3}, [%4];" \
                 : "=r"((r)[0]), "=r"((r)[1]), "=r"((r)[2]), "=r"((r)[3]) \
                 : "r"(addr))
#define LDSM_X2T(r, addr) \
    asm volatile("ldmatrix.sync.aligned.m8n8.x2.trans.shared.b16 {%0,%1}, [%2];" \
                 : "=r"((r)[0]), "=r"((r)[1]) : "r"(addr))

__device__ __forceinline__ void mma_bf16(float* c, const uint32_t* a, const uint32_t* b) {
    asm volatile(
        "mma.sync.aligned.m16n8k16.row.col.f32.bf16.bf16.f32 "
        "{%0,%1,%2,%3}, {%4,%5,%6,%7}, {%8,%9}, {%0,%1,%2,%3};"
        : "+f"(c[0]), "+f"(c[1]), "+f"(c[2]), "+f"(c[3])
        : "r"(a[0]), "r"(a[1]), "r"(a[2]), "r"(a[3]), "r"(b[0]), "r"(b[1]));
}

// ---------------------------------------------------------------------------
// Prep: W[p][c][o] f32 -> bf16 hi/lo in padded [c][o] layout
// ---------------------------------------------------------------------------
__global__ void prep_weights(const float* __restrict__ wt) {
    int idx = blockIdx.x * blockDim.x + threadIdx.x;
    if (idx >= NPAIRS * CH * OD) return;
    int p = idx / (CH * OD);
    int r = idx - p * CH * OD;
    int c = r / OD;
    int o = r - c * OD;
    float w = wt[(p * CH + c) * OD + o];
    __nv_bfloat16 h = __float2bfloat16(w);
    __nv_bfloat16 l = __float2bfloat16(w - __bfloat162float(h));
    g_Bhi[p][c * (BSTR / 2) + o] = h;
    g_Blo[p][c * (BSTR / 2) + o] = l;
}

// ---------------------------------------------------------------------------
// Main kernel: one 64-row M tile per CTA, N=128, K = 55 pairs x 64 ch
// ---------------------------------------------------------------------------
__global__ void __launch_bounds__(BDIM, 4)
qconv_hmma(const float* __restrict__ in, float* __restrict__ out) {
    extern __shared__ unsigned char smem[];
    const uint32_t sb = smem_to_u32(smem);
    int* mbase_s = (int*)(smem + MB_OFF);
    int* mmask_s = (int*)(smem + MK_OFF);

    const int tid  = threadIdx.x;
    const int wid  = tid >> 5;
    const int lane = tid & 31;
    const int gm0  = blockIdx.x * MT;

    if (tid < MT) {
        int gm  = gm0 + tid;
        int b   = gm / (HW * HW);
        int rem = gm - b * HW * HW;
        int h   = rem / HW;
        int w   = rem - h * HW;
        mbase_s[tid] = ((b * HW + (h - 1)) * HW + (w - 1)) * CH;
        int mask = 0;
        #pragma unroll
        for (int kk = 0; kk < 9; kk++) {
            int hh = h + kk / 3 - 1, ww = w + kk % 3 - 1;
            if (hh >= 0 && hh < HW && ww >= 0 && ww < HW) mask |= (1 << kk);
        }
        mmask_s[tid] = mask;
    }
    __syncthreads();

    // A-gen mapping: thread owns m row (tid/2) and a 32-channel half
    const int am   = tid >> 1;
    const int c0   = (tid & 1) * 32;
    const int base = mbase_s[am];
    const int mask = mmask_s[am];

    // GEMM mapping: warps 2(M) x 2(N); warp tile 32 x 64
    const int m0 = (wid >> 1) * 32;
    const int n0 = (wid & 1) * 64;
    // ldmatrix per-thread offsets
    const uint32_t aoff = (uint32_t)((m0 + (lane & 15)) * ASTR + (lane >> 4) * 16);
    const uint32_t boff = (uint32_t)((lane & 15) * BSTR + n0 * 2);

    float acc[2][8][4];
    #pragma unroll
    for (int mt = 0; mt < 2; mt++)
        #pragma unroll
        for (int nt = 0; nt < 8; nt++)
            #pragma unroll
            for (int q = 0; q < 4; q++) acc[mt][nt][q] = 0.f;

    for (int p = 0; p < NPAIRS; p++) {
        const int i = cII[p], j = cJJ[p];
        const int kj = j - 1, ki = i - 1;
        const int offj = (j > 0) ? ((kj / 3) * HW + (kj % 3)) * CH : 0;
        const int offi = (i > 0) ? ((ki / 3) * HW + (ki % 3)) * CH : 0;
        const bool vj = (j == 0) || ((mask >> kj) & 1);
        const bool vi = (i == 0) || ((mask >> ki) & 1);

        // ---- stage B tile (straight copy of padded scratch) ----
        {
            const float4* sh = (const float4*)g_Bhi[p];
            const float4* sl = (const float4*)g_Blo[p];
            float4* dh = (float4*)(smem + BH_OFF);
            float4* dl = (float4*)(smem + BL_OFF);
            #pragma unroll
            for (int t = 0; t < 9; t++) {
                int x = tid + t * BDIM;
                if (x < CH * BSTR / 16) { dh[x] = sh[x]; dl[x] = sl[x]; }
            }
        }

        // ---- stage A tile: quad features -> bf16 hi/lo ----
        #pragma unroll
        for (int g = 0; g < 8; g++) {
            const int c = c0 + g * 4;
            float4 sj, si;
            if (j == 0)   sj = make_float4(1.f, 1.f, 1.f, 1.f);
            else if (vj)  sj = *(const float4*)(in + base + offj + c);
            else          sj = make_float4(0.f, 0.f, 0.f, 0.f);
            if (i == 0)   si = make_float4(1.f, 1.f, 1.f, 1.f);
            else if (vi)  si = *(const float4*)(in + base + offi + c);
            else          si = make_float4(0.f, 0.f, 0.f, 0.f);

            float a0 = si.x * sj.x, a1 = si.y * sj.y;
            float a2 = si.z * sj.z, a3 = si.w * sj.w;
            __nv_bfloat16 h0 = __float2bfloat16(a0), h1 = __float2bfloat16(a1);
            __nv_bfloat16 h2 = __float2bfloat16(a2), h3 = __float2bfloat16(a3);
            __nv_bfloat16 l0 = __float2bfloat16(a0 - __bfloat162float(h0));
            __nv_bfloat16 l1 = __float2bfloat16(a1 - __bfloat162float(h1));
            __nv_bfloat16 l2 = __float2bfloat16(a2 - __bfloat162float(h2));
            __nv_bfloat16 l3 = __float2bfloat16(a3 - __bfloat162float(h3));
            __nv_bfloat162 hA = __halves2bfloat162(h0, h1);
            __nv_bfloat162 hB = __halves2bfloat162(h2, h3);
            __nv_bfloat162 lA = __halves2bfloat162(l0, l1);
            __nv_bfloat162 lB = __halves2bfloat162(l2, l3);
            const unsigned off = (unsigned)(am * ASTR + c * 2);
            *(uint2*)(smem + AH_OFF + off) = make_uint2(*(unsigned*)&hA, *(unsigned*)&hB);
            *(uint2*)(smem + AL_OFF + off) = make_uint2(*(unsigned*)&lA, *(unsigned*)&lB);
        }
        __syncthreads();

        // ---- MMA: 4 k16-steps x 8 n-tiles x {hh, lh, hl} ----
        #pragma unroll
        for (int kk = 0; kk < 4; kk++) {
            uint32_t ah0[4], ah1[4], al0[4], al1[4];
            const uint32_t ab = sb + aoff + kk * 32;
            LDSM_X4(ah0, ab + AH_OFF);
            LDSM_X4(ah1, ab + AH_OFF + 16 * ASTR);
            LDSM_X4(al0, ab + AL_OFF);
            LDSM_X4(al1, ab + AL_OFF + 16 * ASTR);
            const uint32_t bb = sb + boff + kk * 16 * BSTR;
            #pragma unroll
            for (int nt = 0; nt < 8; nt++) {
                uint32_t bh[2], bl[2];
                LDSM_X2T(bh, bb + BH_OFF + nt * 16);
                mma_bf16(acc[0][nt], ah0, bh);
                mma_bf16(acc[1][nt], ah1, bh);
                mma_bf16(acc[0][nt], al0, bh);
                mma_bf16(acc[1][nt], al1, bh);
                LDSM_X2T(bl, bb + BL_OFF + nt * 16);
                mma_bf16(acc[0][nt], ah0, bl);
                mma_bf16(acc[1][nt], ah1, bl);
            }
        }
        __syncthreads();   // safe to overwrite SMEM next p
    }

    // ---- epilogue: register accumulators -> global ----
    float* op = out + (size_t)gm0 * OD;
    const int rr = lane >> 2;
    const int cc = (lane & 3) * 2;
    #pragma unroll
    for (int mt = 0; mt < 2; mt++) {
        #pragma unroll
        for (int nt = 0; nt < 8; nt++) {
            const int r0 = m0 + mt * 16 + rr;
            const int cn = n0 + nt * 8 + cc;
            *(float2*)(op + (size_t)r0 * OD + cn) =
                make_float2(acc[mt][nt][0], acc[mt][nt][1]);
            *(float2*)(op + (size_t)(r0 + 8) * OD + cn) =
                make_float2(acc[mt][nt][2], acc[mt][nt][3]);
        }
    }
}

// ---------------------------------------------------------------------------
extern "C" void kernel_launch(void* const* d_in, const int* in_sizes, int n_in,
                              void* d_out, int out_size) {
    const float* in = (const float*)d_in[0];
    const float* wt = (const float*)d_in[1];
    if (n_in >= 2 && in_sizes[0] == NPAIRS * CH * OD) {  // defensive order check
        const float* t = in; in = wt; wt = t;
    }
    float* out = (float*)d_out;

    prep_weights<<<(NPAIRS * CH * OD + 255) / 256, 256>>>(wt);

    cudaFuncSetAttribute(qconv_hmma,
                         cudaFuncAttributeMaxDynamicSharedMemorySize, SMEM_TOTAL);
    qconv_hmma<<<NTILES, BDIM, SMEM_TOTAL>>>(in, out);
}